// round 1
// baseline (speedup 1.0000x reference)
#include <cuda_runtime.h>
#include <cuda_bf16.h>
#include <cstddef>

#define NALGOS  64
#define NTASKS  1024
#define LX_LEN  512
#define TSTEPS  513   // 1 (zeros) + 512 steps
#define BUF     16

// One CTA per algo. Thread j owns result[a,j] in a register across all 512
// steps. The only cross-thread value per step is pp = sig_{t-1}[a, task_t]:
// the owner thread (j == task) publishes it to a double-buffered smem slot,
// so one __syncthreads() per step suffices.
__global__ void __launch_bounds__(NTASKS, 1)
clamp_scan_kernel(const int*   __restrict__ lx,
                  const float* __restrict__ tm,      // [NTASKS][NTASKS]
                  const float* __restrict__ diff,    // [NTASKS]
                  const float* __restrict__ eff_g,   // [NALGOS]
                  const float* __restrict__ mem_g,   // [NALGOS]
                  const float* __restrict__ boost_g, // [NALGOS]
                  float*       __restrict__ out)     // [NALGOS][NTASKS][TSTEPS]
{
    __shared__ int   lx_sh[LX_LEN + 1];
    __shared__ float pp_sh[2];

    const int a = blockIdx.x;
    const int j = threadIdx.x;

    if (j < LX_LEN) lx_sh[j] = lx[j];
    if (j == 0) { lx_sh[LX_LEN] = 0; pp_sh[0] = 0.0f; }

    const float eff   = eff_g[a];
    const float mem   = mem_g[a];
    const float boost = boost_g[a];
    const float nid   = -1.0f / diff[j];   // -(1/diff), folds negation into exp arg

    float* outp = out + ((size_t)a * NTASKS + j) * TSTEPS;
    outp[0] = 0.0f;        // t=0 slice is zeros
    outp += 1;

    float result = 0.0f;
    float buf[BUF];

    __syncthreads();

    // Prefetch row for step 0.
    float rcur = tm[(size_t)lx_sh[0] * NTASKS + j];

    for (int t0 = 0; t0 < LX_LEN; t0 += BUF) {
        #pragma unroll
        for (int k = 0; k < BUF; ++k) {
            const int t      = t0 + k;
            const int task_n = lx_sh[t + 1];           // next step's task
            // Prefetch next step's row early (covered by this step's latency).
            const float rnext = tm[(size_t)task_n * NTASKS + j];

            const float pp   = pp_sh[t & 1];           // sig_{t-1}[a, task_t]
            const float coef = fmaf(pp, boost, eff);
            result = fmaf(result, mem, rcur * coef);

            // sig = 2*sigmoid(result/diff) - 1 = 2/(1 + e^{-result/diff}) - 1
            const float e = __expf(result * nid);
            float r;
            asm("rcp.approx.f32 %0, %1;" : "=f"(r) : "f"(e + 1.0f));
            const float sig = fmaf(2.0f, r, -1.0f);

            buf[k] = sig;
            if (j == task_n) pp_sh[(t + 1) & 1] = sig; // publish for next step
            rcur = rnext;
            __syncthreads();
        }
        // Flush 16 contiguous t-values per thread (register-staged for
        // sector-efficient writes against the odd 513 stride).
        #pragma unroll
        for (int k = 0; k < BUF; ++k) outp[t0 + k] = buf[k];
    }
}

extern "C" void kernel_launch(void* const* d_in, const int* in_sizes, int n_in,
                              void* d_out, int out_size)
{
    const int*   lx    = (const int*)  d_in[0];
    const float* tm    = (const float*)d_in[1];
    const float* diff  = (const float*)d_in[2];
    const float* eff   = (const float*)d_in[3];
    const float* mem   = (const float*)d_in[4];
    const float* boost = (const float*)d_in[5];
    float*       out   = (float*)d_out;

    clamp_scan_kernel<<<NALGOS, NTASKS>>>(lx, tm, diff, eff, mem, boost, out);
}

// round 4
// speedup vs baseline: 1.6944x; 1.6944x over previous
#include <cuda_runtime.h>
#include <cuda_bf16.h>
#include <cstddef>

#define NALGOS  64
#define NTASKS  1024
#define LX_LEN  512
#define TSTEPS  513       // 1 (zeros) + 512 steps
#define TW      32        // tile of t-steps staged in smem before flush
#define PITCH   1025      // padded row pitch (floats) -> conflict-free both ways

// One CTA per algo. Thread j owns result[a,j] in a register across all 512
// steps. Per step, the single cross-thread scalar pp = sig_{t-1}[a, task_t]
// is relayed via a double-buffered smem slot (one __syncthreads per step).
// Output sigs are staged in a [TW][PITCH] smem tile and flushed with
// warp-coalesced 128B stores (transpose), fixing the stride-513 scatter.
__global__ void __launch_bounds__(NTASKS, 1)
clamp_scan_kernel(const int*   __restrict__ lx,
                  const float* __restrict__ tm,      // [NTASKS][NTASKS]
                  const float* __restrict__ diff,    // [NTASKS]
                  const float* __restrict__ eff_g,   // [NALGOS]
                  const float* __restrict__ mem_g,   // [NALGOS]
                  const float* __restrict__ boost_g, // [NALGOS]
                  float*       __restrict__ out)     // [NALGOS][NTASKS][TSTEPS]
{
    extern __shared__ float sig_sh[];                // [TW][PITCH]
    __shared__ int   lx_sh[LX_LEN + 2];
    __shared__ float pp_sh[2];

    const int a = blockIdx.x;
    const int j = threadIdx.x;

    if (j < LX_LEN) lx_sh[j] = lx[j];
    if (j == 0) { lx_sh[LX_LEN] = 0; lx_sh[LX_LEN + 1] = 0; pp_sh[0] = 0.0f; }

    const float eff   = eff_g[a];
    const float mem   = mem_g[a];
    const float boost = boost_g[a];
    // exp arg scale: sig = 2/(1 + 2^(result * nid)) - 1, nid = -log2(e)/diff
    const float nid   = -1.4426950408889634f / diff[j];

    // t=0 slice is zeros.
    out[((size_t)a * NTASKS + j) * TSTEPS] = 0.0f;

    float result = 0.0f;

    __syncthreads();

    // Prefetch rows for steps 0 and 1 (distance-2 covers L2 latency).
    float r0 = tm[(size_t)lx_sh[0] * NTASKS + j];
    float r1 = tm[(size_t)lx_sh[1] * NTASKS + j];

    const int w    = j >> 5;
    const int lane = j & 31;

    for (int t0 = 0; t0 < LX_LEN; t0 += TW) {
        #pragma unroll
        for (int k = 0; k < TW; ++k) {
            const int t      = t0 + k;
            const int task_n = lx_sh[t + 1];               // next step's task
            const float r2   = tm[(size_t)lx_sh[t + 2] * NTASKS + j];

            const float pp   = pp_sh[t & 1];               // sig_{t-1}[a, task_t]
            const float coef = fmaf(pp, boost, eff);
            result = fmaf(result, mem, r0 * coef);

            float e;
            asm("ex2.approx.f32 %0, %1;" : "=f"(e) : "f"(result * nid));
            float rcp;
            asm("rcp.approx.f32 %0, %1;" : "=f"(rcp) : "f"(e + 1.0f));
            const float sig = fmaf(2.0f, rcp, -1.0f);

            sig_sh[k * PITCH + j] = sig;
            if (j == task_n) pp_sh[(t + 1) & 1] = sig;     // publish for next step
            r0 = r1; r1 = r2;
            __syncthreads();
        }

        // Coalesced flush: warp w writes rows [w*32, w*32+32); for each row,
        // lane L stores t-value t0+L -> 128B contiguous per warp-instruction.
        #pragma unroll
        for (int i = 0; i < 32; ++i) {
            const int row = (w << 5) + i;
            const float v = sig_sh[lane * PITCH + row];    // bank (lane+row)%32: conflict-free
            out[((size_t)a * NTASKS + row) * TSTEPS + 1 + t0 + lane] = v;
        }
        __syncthreads();   // tile consumed before next fill
    }
}

extern "C" void kernel_launch(void* const* d_in, const int* in_sizes, int n_in,
                              void* d_out, int out_size)
{
    const int*   lx    = (const int*)  d_in[0];
    const float* tm    = (const float*)d_in[1];
    const float* diff  = (const float*)d_in[2];
    const float* eff   = (const float*)d_in[3];
    const float* mem   = (const float*)d_in[4];
    const float* boost = (const float*)d_in[5];
    float*       out   = (float*)d_out;

    const int smem_bytes = TW * PITCH * (int)sizeof(float);   // 131,200 B
    cudaFuncSetAttribute(clamp_scan_kernel,
                         cudaFuncAttributeMaxDynamicSharedMemorySize, smem_bytes);
    clamp_scan_kernel<<<NALGOS, NTASKS, smem_bytes>>>(lx, tm, diff, eff, mem, boost, out);
}

// round 5
// speedup vs baseline: 1.7241x; 1.0175x over previous
#include <cuda_runtime.h>
#include <cstddef>

#define NALGOS 64
#define NTASKS 1024
#define LXN    512
#define TSTEPS 513
#define L2E    1.44269504088896f

// Scratch (static device globals are allowed; zero-initialized).
__device__ float g_Gp[516 * 512];          // gathered G, vec4 layout, +pad rows for prefetch
__device__ float g_dvec[512];              // -log2e / diff[lx[s]]
__device__ float g_coef[NALGOS * LXN];     // coef_t per algo (phase-1 output)

// ---------------------------------------------------------------------------
// prep: G[t][s] = tm[lx[t]][lx[s]], stored so that lane L can LDG.128 its
// 16 slots (slot s: lane=s%32, i=s/32; quad q=i/4, b=i%4):
//   idx(t,s) = t*512 + (s>>7)*128 + (s&31)*4 + ((s>>5)&3)
// ---------------------------------------------------------------------------
__global__ void prep_kernel(const int* __restrict__ lx,
                            const float* __restrict__ tm,
                            const float* __restrict__ diff)
{
    const int t = blockIdx.x;
    const int s = threadIdx.x;
    const int ls = lx[s];
    const int lt = lx[t];
    g_Gp[t * 512 + ((s >> 7) << 7) + ((s & 31) << 2) + ((s >> 5) & 3)]
        = tm[(size_t)lt * NTASKS + ls];
    if (t == 0) g_dvec[s] = -L2E / diff[ls];
}

// ---------------------------------------------------------------------------
// phase 1: one warp per algo runs the serial scalar chain.
// Iteration n (= step t = n): publish sig of slot n (value after step n-1),
// broadcast via shfl from lane n%32, form coef_n, update all 512 slot states.
// Shadow register tracks the lane's block-m slot (32m+lane) so the publish
// never needs a runtime-indexed register array.
// ---------------------------------------------------------------------------
__global__ void __launch_bounds__(32, 1)
phase1_kernel(const float* __restrict__ eff_g,
              const float* __restrict__ mem_g,
              const float* __restrict__ boost_g)
{
    const int a    = blockIdx.x;
    const int lane = threadIdx.x;

    const float eff   = eff_g[a];
    const float mem   = mem_g[a];
    const float boost = boost_g[a];

    float res[16];
    #pragma unroll
    for (int i = 0; i < 16; ++i) res[i] = 0.0f;

    const float4* __restrict__ Gp4 = (const float4*)g_Gp;

    // Distance-2 prefetch buffers (compile-time selected by k&1).
    float4 gb0[4], gb1[4];
    float  gs0, gs1;
    #pragma unroll
    for (int q = 0; q < 4; ++q) gb0[q] = Gp4[0 * 128 + q * 32 + lane];
    #pragma unroll
    for (int q = 0; q < 4; ++q) gb1[q] = Gp4[1 * 128 + q * 32 + lane];
    gs0 = g_Gp[0 * 512 + lane * 4];            // n=0: m=0 -> q=0,b=0
    gs1 = g_Gp[1 * 512 + lane * 4];            // n=1: m=0

    for (int m = 0; m < 16; ++m) {
        // shadow = res[m] without runtime indexing (16 predicated moves)
        float shadow = res[0];
        #pragma unroll
        for (int i = 1; i < 16; ++i) if (i == m) shadow = res[i];

        const float nds = g_dvec[32 * m + lane];   // -log2e/diff at lane's slot
        float myc = 0.0f;

        #pragma unroll
        for (int k = 0; k < 32; ++k) {
            const int n = 32 * m + k;

            // publish slot n: every lane computes sig of its own shadow
            const float x = shadow * nds;
            float e;  asm("ex2.approx.f32 %0, %1;" : "=f"(e)  : "f"(x));
            float rc; asm("rcp.approx.f32 %0, %1;" : "=f"(rc) : "f"(e + 1.0f));
            const float sigv = fmaf(2.0f, rc, -1.0f);
            const float pp   = __shfl_sync(0xffffffffu, sigv, k);
            const float coef = fmaf(pp, boost, eff);
            if (lane == k) myc = coef;

            // grab current step's G values, then prefetch n+2 into same slot
            float4 c0, c1, c2, c3; float gsc;
            const int np = n + 2;
            const int mp = np >> 5;
            if (k & 1) {
                c0 = gb1[0]; c1 = gb1[1]; c2 = gb1[2]; c3 = gb1[3]; gsc = gs1;
                #pragma unroll
                for (int q = 0; q < 4; ++q) gb1[q] = Gp4[np * 128 + q * 32 + lane];
                gs1 = g_Gp[np * 512 + ((mp >> 2) << 7) + lane * 4 + (mp & 3)];
            } else {
                c0 = gb0[0]; c1 = gb0[1]; c2 = gb0[2]; c3 = gb0[3]; gsc = gs0;
                #pragma unroll
                for (int q = 0; q < 4; ++q) gb0[q] = Gp4[np * 128 + q * 32 + lane];
                gs0 = g_Gp[np * 512 + ((mp >> 2) << 7) + lane * 4 + (mp & 3)];
            }

            // step n: update all tracked slots + shadow
            res[ 0] = fmaf(res[ 0], mem, c0.x * coef);
            res[ 1] = fmaf(res[ 1], mem, c0.y * coef);
            res[ 2] = fmaf(res[ 2], mem, c0.z * coef);
            res[ 3] = fmaf(res[ 3], mem, c0.w * coef);
            res[ 4] = fmaf(res[ 4], mem, c1.x * coef);
            res[ 5] = fmaf(res[ 5], mem, c1.y * coef);
            res[ 6] = fmaf(res[ 6], mem, c1.z * coef);
            res[ 7] = fmaf(res[ 7], mem, c1.w * coef);
            res[ 8] = fmaf(res[ 8], mem, c2.x * coef);
            res[ 9] = fmaf(res[ 9], mem, c2.y * coef);
            res[10] = fmaf(res[10], mem, c2.z * coef);
            res[11] = fmaf(res[11], mem, c2.w * coef);
            res[12] = fmaf(res[12], mem, c3.x * coef);
            res[13] = fmaf(res[13], mem, c3.y * coef);
            res[14] = fmaf(res[14], mem, c3.z * coef);
            res[15] = fmaf(res[15], mem, c3.w * coef);
            shadow  = fmaf(shadow,  mem, gsc  * coef);
        }
        g_coef[a * LXN + 32 * m + lane] = myc;     // coalesced, once per block
    }
}

// ---------------------------------------------------------------------------
// phase 2: barrier-free independent scans. grid (2 chunks, 64 algos) x 512.
// Thread owns one (a, j); coef sequence read from smem; output staged in a
// transposed smem tile and flushed with warp-coalesced 128B stores.
// ---------------------------------------------------------------------------
#define P2_TW    32
#define P2_PITCH 513
#define P2_SMEM  ((P2_TW * P2_PITCH + 512) * 4 + 514 * 4)

__global__ void __launch_bounds__(512, 1)
phase2_kernel(const int*   __restrict__ lx,
              const float* __restrict__ tm,
              const float* __restrict__ diff,
              const float* __restrict__ mem_g,
              float*       __restrict__ out)
{
    extern __shared__ float smem[];
    float* tile = smem;                        // [32][513]
    float* csh  = smem + P2_TW * P2_PITCH;     // [512]
    int*   lxsh = (int*)(csh + 512);           // [514]

    const int tid = threadIdx.x;
    const int c   = blockIdx.x;                // j-chunk (0/1)
    const int a   = blockIdx.y;                // algo
    const int j   = c * 512 + tid;

    const float mem = mem_g[a];
    const float nid = -L2E / diff[j];

    csh[tid]  = g_coef[a * LXN + tid];
    lxsh[tid] = lx[tid];
    if (tid < 2) lxsh[512 + tid] = 0;
    out[((size_t)a * NTASKS + j) * TSTEPS] = 0.0f;   // t=0 slice
    __syncthreads();

    float result = 0.0f;
    float r0 = tm[(size_t)lxsh[0] * NTASKS + j];
    float r1 = tm[(size_t)lxsh[1] * NTASKS + j];

    const int w    = tid >> 5;
    const int lane = tid & 31;

    for (int t0 = 0; t0 < LXN; t0 += P2_TW) {
        #pragma unroll
        for (int k = 0; k < P2_TW; ++k) {
            const int t = t0 + k;
            const float r2 = tm[(size_t)lxsh[t + 2] * NTASKS + j];
            const float cf = csh[t];
            result = fmaf(result, mem, r0 * cf);
            const float x = result * nid;
            float e;  asm("ex2.approx.f32 %0, %1;" : "=f"(e)  : "f"(x));
            float rc; asm("rcp.approx.f32 %0, %1;" : "=f"(rc) : "f"(e + 1.0f));
            tile[k * P2_PITCH + tid] = fmaf(2.0f, rc, -1.0f);
            r0 = r1; r1 = r2;
        }
        __syncthreads();
        // warp w flushes rows [32w, 32w+32): 128B contiguous per instruction
        #pragma unroll 4
        for (int i = 0; i < 32; ++i) {
            const int row = (w << 5) + i;
            out[((size_t)a * NTASKS + c * 512 + row) * TSTEPS + 1 + t0 + lane]
                = tile[lane * P2_PITCH + row];
        }
        __syncthreads();
    }
}

extern "C" void kernel_launch(void* const* d_in, const int* in_sizes, int n_in,
                              void* d_out, int out_size)
{
    const int*   lx    = (const int*)  d_in[0];
    const float* tm    = (const float*)d_in[1];
    const float* diff  = (const float*)d_in[2];
    const float* eff   = (const float*)d_in[3];
    const float* mem   = (const float*)d_in[4];
    const float* boost = (const float*)d_in[5];
    float*       out   = (float*)d_out;

    prep_kernel<<<512, 512>>>(lx, tm, diff);
    phase1_kernel<<<NALGOS, 32>>>(eff, mem, boost);

    cudaFuncSetAttribute(phase2_kernel,
                         cudaFuncAttributeMaxDynamicSharedMemorySize, P2_SMEM);
    dim3 g2(2, NALGOS);
    phase2_kernel<<<g2, 512, P2_SMEM>>>(lx, tm, diff, mem, out);
}

// round 6
// speedup vs baseline: 3.0337x; 1.7597x over previous
#include <cuda_runtime.h>
#include <cstddef>

#define NALGOS 64
#define NTASKS 1024
#define LXN    512
#define TSTEPS 513
#define L2E    1.44269504088896f

// Scratch (__device__ globals: allowed, no allocation).
__device__ float g_GT[LXN * LXN];        // GT[s][t] = tm[lx[t]][lx[s]]
__device__ float g_dvec[LXN];            // -log2e / diff[lx[s]]
__device__ float g_coef[NALGOS * LXN];   // phase-1 output

// ---------------------------------------------------------------------------
// prep: build GT (slot-major) + dvec. Writes coalesced; reads are the
// inherent random gather of tm[lx[t]][lx[s]].
// ---------------------------------------------------------------------------
__global__ void prep_kernel(const int*   __restrict__ lx,
                            const float* __restrict__ tm,
                            const float* __restrict__ diff)
{
    const int s  = blockIdx.x;
    const int t  = threadIdx.x;
    const int ls = lx[s];
    const int lt = lx[t];
    g_GT[s * LXN + t] = tm[(size_t)lt * NTASKS + ls];
    if (s == 0) g_dvec[t] = -L2E / diff[lt];
}

// ---------------------------------------------------------------------------
// phase 1: one CTA per algo, 544 threads.
//   warp 0 (leader): serial coef chain over 16 blocks of 32 steps, carrying
//     the current block's 32 slot-states replicated in registers (triangular
//     updates, no shfl on the critical path).
//   warps 1..16 (followers): warp w owns slot block w-1; after each leader
//     block, applies the 32 new coefs to its slot as a batched update
//     res = res*mem^32 + sum_i G[t_i][s]*coef_i*mem^(31-i), with G prefetched
//     one block ahead.
// ---------------------------------------------------------------------------
#define P1_THREADS 544

__global__ void __launch_bounds__(P1_THREADS, 1)
phase1_kernel(const float* __restrict__ eff_g,
              const float* __restrict__ mem_g,
              const float* __restrict__ boost_g)
{
    __shared__ float Gt_sh[32][33];   // [slot-local i][step-local k] of current block
    __shared__ float coef_sh[LXN];
    __shared__ float dvec_sh[LXN];
    __shared__ float handoff[32];
    __shared__ float mp_sh[32];       // mem^(31-i)
    __shared__ float mem32_sh;

    const int tid  = threadIdx.x;
    const int w    = tid >> 5;
    const int lane = tid & 31;
    const int a    = blockIdx.x;

    const float eff   = eff_g[a];
    const float mem   = mem_g[a];
    const float boost = boost_g[a];

    if (tid < LXN) dvec_sh[tid] = g_dvec[tid];
    if (tid == 0) {
        float p = 1.0f;
        for (int i = 31; i >= 0; --i) { mp_sh[i] = p; p *= mem; }
        mem32_sh = p;                 // mem^32
    }
    // stage tile for block 0: Gt_sh[i][k] = GT[i][k]
    for (int i = tid; i < 1024; i += P1_THREADS)
        Gt_sh[i >> 5][i & 31] = g_GT[(i >> 5) * LXN + (i & 31)];

    const int fb   = w - 1;           // follower's block (w>=1)
    const int slot = fb * 32 + lane;
    float res = 0.0f;                 // follower slot state

    // follower: prefetch G row chunk for block-0 coefs
    float4 gt[8];
    if (w >= 1) {
        const float4* p = (const float4*)(g_GT + (size_t)slot * LXN);
        #pragma unroll
        for (int q = 0; q < 8; ++q) gt[q] = p[q];
    }
    __syncthreads();

    float tile_reg[2];

    for (int m = 0; m < 16; ++m) {
        // ---- pre-block: followers apply block m-1 coefs; stage tile m ----
        if (m > 0) {
            {   // STS tile m from regs (followers hold tile_reg)
                int q = 0;
                for (int i = tid - 32; i >= 0 && i < 1024; i += 512, ++q)
                    Gt_sh[i >> 5][i & 31] = tile_reg[q];
            }
            if (w >= 1 && fb >= m) {
                const float* cf = coef_sh + (m - 1) * 32;
                float a0 = 0.f, a1 = 0.f, a2 = 0.f, a3 = 0.f;
                const float* gf = (const float*)gt;
                #pragma unroll
                for (int i = 0; i < 32; i += 4) {
                    a0 = fmaf(gf[i + 0], cf[i + 0] * mp_sh[i + 0], a0);
                    a1 = fmaf(gf[i + 1], cf[i + 1] * mp_sh[i + 1], a1);
                    a2 = fmaf(gf[i + 2], cf[i + 2] * mp_sh[i + 2], a2);
                    a3 = fmaf(gf[i + 3], cf[i + 3] * mp_sh[i + 3], a3);
                }
                res = fmaf(res, mem32_sh, (a0 + a1) + (a2 + a3));
            }
            if (w >= 1 && fb == m) handoff[lane] = res;
        } else {
            if (w == 1) handoff[lane] = res;    // zeros for block 0
        }
        __syncthreads();   // handoff + tile + batch visible

        // ---- leader runs 32 serial steps; followers prefetch ahead ----
        if (w == 0) {
            float b[32];
            #pragma unroll
            for (int i = 0; i < 32; ++i) b[i] = handoff[i];
            #pragma unroll
            for (int k = 0; k < 32; ++k) {
                const float x = b[k] * dvec_sh[m * 32 + k];
                float e;  asm("ex2.approx.f32 %0, %1;" : "=f"(e)  : "f"(x));
                float rc; asm("rcp.approx.f32 %0, %1;" : "=f"(rc) : "f"(e + 1.0f));
                const float pp   = fmaf(2.0f, rc, -1.0f);
                const float coef = fmaf(pp, boost, eff);
                if (lane == 0) coef_sh[m * 32 + k] = coef;
                #pragma unroll
                for (int i = k + 1; i < 32; ++i)
                    b[i] = fmaf(b[i], mem, Gt_sh[i][k] * coef);
            }
        } else {
            // prefetch G chunk for block-m coefs (used next iteration)
            if (fb > m) {
                const float4* p = (const float4*)(g_GT + (size_t)slot * LXN + m * 32);
                #pragma unroll
                for (int q = 0; q < 8; ++q) gt[q] = p[q];
            } else if (fb == m) {
                // this follower's own-block G (needed to apply block m's coefs
                // before handoff... not needed: block m slots publish during
                // block m; after that they are dead. No load.
            }
            // prefetch next leader tile (block m+1 diagonal 32x32)
            if (m < 15) {
                const int base = 32 * (m + 1);
                int q = 0;
                for (int i = tid - 32; i >= 0 && i < 1024; i += 512, ++q)
                    tile_reg[q] = g_GT[(size_t)(base + (i >> 5)) * LXN + base + (i & 31)];
            }
        }
        __syncthreads();   // coef block m complete
    }

    if (tid < LXN) g_coef[a * LXN + tid] = coef_sh[tid];
}

// ---------------------------------------------------------------------------
// phase 2: independent scans. grid (4 j-chunks, 64 algos) x 256 threads.
// Distance-4 row prefetch; transposed smem tile flush for coalesced stores.
// ---------------------------------------------------------------------------
#define P2_TW 32

__global__ void __launch_bounds__(256, 2)
phase2_kernel(const int*   __restrict__ lx,
              const float* __restrict__ tm,
              const float* __restrict__ diff,
              const float* __restrict__ mem_g,
              float*       __restrict__ out)
{
    __shared__ float tile[P2_TW][257];
    __shared__ float csh[LXN];
    __shared__ int   lxsh[LXN + 4];

    const int tid = threadIdx.x;
    const int c   = blockIdx.x;             // 0..3
    const int a   = blockIdx.y;
    const int j   = c * 256 + tid;

    const float mem = mem_g[a];
    const float nid = -L2E / diff[j];

    for (int i = tid; i < LXN; i += 256) { csh[i] = g_coef[a * LXN + i]; lxsh[i] = lx[i]; }
    if (tid < 4) lxsh[LXN + tid] = 0;
    out[((size_t)a * NTASKS + j) * TSTEPS] = 0.0f;     // t=0 slice
    __syncthreads();

    float result = 0.0f;
    float r0 = tm[(size_t)lxsh[0] * NTASKS + j];
    float r1 = tm[(size_t)lxsh[1] * NTASKS + j];
    float r2 = tm[(size_t)lxsh[2] * NTASKS + j];
    float r3 = tm[(size_t)lxsh[3] * NTASKS + j];

    const int w    = tid >> 5;
    const int lane = tid & 31;

    for (int t0 = 0; t0 < LXN; t0 += P2_TW) {
        #pragma unroll
        for (int k = 0; k < P2_TW; ++k) {
            const int t = t0 + k;
            float cur;
            if      ((k & 3) == 0) cur = r0;
            else if ((k & 3) == 1) cur = r1;
            else if ((k & 3) == 2) cur = r2;
            else                   cur = r3;
            const float rn = tm[(size_t)lxsh[t + 4] * NTASKS + j];
            if      ((k & 3) == 0) r0 = rn;
            else if ((k & 3) == 1) r1 = rn;
            else if ((k & 3) == 2) r2 = rn;
            else                   r3 = rn;

            result = fmaf(result, mem, cur * csh[t]);
            float e;  asm("ex2.approx.f32 %0, %1;" : "=f"(e)  : "f"(result * nid));
            float rc; asm("rcp.approx.f32 %0, %1;" : "=f"(rc) : "f"(e + 1.0f));
            tile[k][tid] = fmaf(2.0f, rc, -1.0f);
        }
        __syncthreads();
        // warp w flushes j-local rows [32w, 32w+32): 128B contiguous per STG
        #pragma unroll 4
        for (int i = 0; i < 32; ++i) {
            const int row = (w << 5) + i;
            out[((size_t)a * NTASKS + c * 256 + row) * TSTEPS + 1 + t0 + lane]
                = tile[lane][row];
        }
        __syncthreads();
    }
}

extern "C" void kernel_launch(void* const* d_in, const int* in_sizes, int n_in,
                              void* d_out, int out_size)
{
    const int*   lx    = (const int*)  d_in[0];
    const float* tm    = (const float*)d_in[1];
    const float* diff  = (const float*)d_in[2];
    const float* eff   = (const float*)d_in[3];
    const float* mem   = (const float*)d_in[4];
    const float* boost = (const float*)d_in[5];
    float*       out   = (float*)d_out;

    prep_kernel<<<LXN, LXN>>>(lx, tm, diff);
    phase1_kernel<<<NALGOS, P1_THREADS>>>(eff, mem, boost);
    dim3 g2(4, NALGOS);
    phase2_kernel<<<g2, 256>>>(lx, tm, diff, mem, out);
}

// round 7
// speedup vs baseline: 3.1365x; 1.0339x over previous
#include <cuda_runtime.h>
#include <cstddef>

#define NALGOS 64
#define NTASKS 1024
#define LXN    512
#define TSTEPS 513
#define L2E    1.44269504088896f

__device__ float g_GT[LXN * LXN];        // GT[s][t] = tm[lx[t]][lx[s]]
__device__ float g_dvec[LXN];            // -log2e / diff[lx[s]]
__device__ float g_coef[NALGOS * LXN];   // phase-1 output

// Shifts the ncu -s 5 capture slot so a real kernel gets profiled.
__global__ void dummy_kernel() {}

// ---------------------------------------------------------------------------
// prep: build GT (slot-major, coalesced writes) + dvec.
// ---------------------------------------------------------------------------
__global__ void prep_kernel(const int*   __restrict__ lx,
                            const float* __restrict__ tm,
                            const float* __restrict__ diff)
{
    const int s  = blockIdx.x;
    const int t  = threadIdx.x;
    const int ls = lx[s];
    const int lt = lx[t];
    g_GT[s * LXN + t] = tm[(size_t)lt * NTASKS + ls];
    if (s == 0) g_dvec[t] = -L2E / diff[lt];
}

// ---------------------------------------------------------------------------
// phase 1: one CTA per algo, 544 threads. Leader warp runs the serial chain
// with the affine-in-rcp trick: x_{k+1} = A + B*r_k, A/B precomputable, so
// the chain is fma->ex2->add->rcp = 40 cyc/step. States carried dvec-scaled
// (bd = b * dvec) on a dvec-prescaled tile Gd. Followers batch-apply each
// finished 32-coef block to their future slots and hand off bd at their turn.
// ---------------------------------------------------------------------------
#define P1_THREADS 544

__global__ void __launch_bounds__(P1_THREADS, 1)
phase1_kernel(const float* __restrict__ eff_g,
              const float* __restrict__ mem_g,
              const float* __restrict__ boost_g)
{
    __shared__ float Gd_sh[32][33];   // dvec-scaled diagonal tile of current block
    __shared__ float coef_sh[LXN];
    __shared__ float dvec_sh[LXN];
    __shared__ float handoff[32];
    __shared__ float mp_sh[32];       // mem^(31-i)
    __shared__ float mem32_sh;

    const int tid  = threadIdx.x;
    const int w    = tid >> 5;
    const int lane = tid & 31;
    const int a    = blockIdx.x;

    const float eff   = eff_g[a];
    const float mem   = mem_g[a];
    const float boost = boost_g[a];
    const float c0    = eff - boost;     // coef = c0 + c1 * rcp(1+e)
    const float c1    = 2.0f * boost;

    if (tid < LXN) dvec_sh[tid] = g_dvec[tid];
    if (tid == 0) {
        float p = 1.0f;
        for (int i = 31; i >= 0; --i) { mp_sh[i] = p; p *= mem; }
        mem32_sh = p;
    }
    // stage dvec-scaled tile for block 0
    for (int i = tid; i < 1024; i += P1_THREADS) {
        const int r_ = i >> 5, k_ = i & 31;
        Gd_sh[r_][k_] = g_GT[r_ * LXN + k_] * g_dvec[r_];
    }

    const int fb   = w - 1;           // follower's slot block (w>=1)
    const int slot = fb * 32 + lane;
    float res = 0.0f;

    float4 gt[8];                     // raw G row chunk for batch updates
    if (w >= 1) {
        const float4* p = (const float4*)(g_GT + (size_t)slot * LXN);
        #pragma unroll
        for (int q = 0; q < 8; ++q) gt[q] = p[q];
    }
    __syncthreads();

    float tile_reg[2];

    for (int m = 0; m < 16; ++m) {
        if (m > 0) {
            {   // stage tile m from prefetched regs
                int q = 0;
                for (int i = tid - 32; i >= 0 && i < 1024; i += 512, ++q)
                    Gd_sh[i >> 5][i & 31] = tile_reg[q];
            }
            if (w >= 1 && fb >= m) {
                const float* cf = coef_sh + (m - 1) * 32;
                float a0 = 0.f, a1 = 0.f, a2 = 0.f, a3 = 0.f;
                const float* gf = (const float*)gt;
                #pragma unroll
                for (int i = 0; i < 32; i += 4) {
                    a0 = fmaf(gf[i + 0], cf[i + 0] * mp_sh[i + 0], a0);
                    a1 = fmaf(gf[i + 1], cf[i + 1] * mp_sh[i + 1], a1);
                    a2 = fmaf(gf[i + 2], cf[i + 2] * mp_sh[i + 2], a2);
                    a3 = fmaf(gf[i + 3], cf[i + 3] * mp_sh[i + 3], a3);
                }
                res = fmaf(res, mem32_sh, (a0 + a1) + (a2 + a3));
            }
            if (w >= 1 && fb == m) handoff[lane] = res * dvec_sh[slot];
        } else {
            if (w == 1) handoff[lane] = 0.0f;
        }
        __syncthreads();

        if (w == 0) {
            float bd[32];
            #pragma unroll
            for (int i = 0; i < 32; ++i) bd[i] = handoff[i];
            const int tb = m * 32;

            // step 0 of block
            float e, r, coef;
            float x = bd[0];
            asm("ex2.approx.f32 %0, %1;" : "=f"(e) : "f"(x));
            asm("rcp.approx.f32 %0, %1;" : "=f"(r) : "f"(e + 1.0f));
            coef = fmaf(c1, r, c0);
            if (lane == 0) coef_sh[tb] = coef;
            #pragma unroll
            for (int i = 2; i < 32; ++i)
                bd[i] = fmaf(bd[i], mem, Gd_sh[i][0] * coef);

            // steps 1..31: x = A + B*r (A,B off the critical path)
            #pragma unroll
            for (int k = 1; k < 32; ++k) {
                const float g = Gd_sh[k][k - 1];
                const float A = fmaf(bd[k], mem, g * c0);
                const float B = g * c1;
                x = fmaf(B, r, A);
                asm("ex2.approx.f32 %0, %1;" : "=f"(e) : "f"(x));
                asm("rcp.approx.f32 %0, %1;" : "=f"(r) : "f"(e + 1.0f));
                coef = fmaf(c1, r, c0);
                if (lane == 0) coef_sh[tb + k] = coef;
                #pragma unroll
                for (int i = k + 2; i < 32; ++i)
                    bd[i] = fmaf(bd[i], mem, Gd_sh[i][k] * coef);
            }
        } else {
            if (fb > m) {   // prefetch raw-G chunk for block-m coefs
                const float4* p = (const float4*)(g_GT + (size_t)slot * LXN + m * 32);
                #pragma unroll
                for (int q = 0; q < 8; ++q) gt[q] = p[q];
            }
            if (m < 15) {   // prefetch next diagonal tile, dvec-scaled
                const int base = 32 * (m + 1);
                int q = 0;
                for (int i = tid - 32; i >= 0 && i < 1024; i += 512, ++q) {
                    const int s_ = base + (i >> 5);
                    tile_reg[q] = g_GT[(size_t)s_ * LXN + base + (i & 31)] * dvec_sh[s_];
                }
            }
        }
        __syncthreads();
    }

    if (tid < LXN) g_coef[a * LXN + tid] = coef_sh[tid];
}

// ---------------------------------------------------------------------------
// phase 2: independent scans. grid (8 j-chunks, 64 algos) x 128 threads,
// occ 4 -> all 148 SMs, 8 warps/SMSP to hide L2 + MUFU latency.
// ---------------------------------------------------------------------------
#define P2_TW 32

__global__ void __launch_bounds__(128, 4)
phase2_kernel(const int*   __restrict__ lx,
              const float* __restrict__ tm,
              const float* __restrict__ diff,
              const float* __restrict__ mem_g,
              float*       __restrict__ out)
{
    __shared__ float tile[P2_TW][129];
    __shared__ float csh[LXN];
    __shared__ int   lxsh[LXN + 4];

    const int tid = threadIdx.x;
    const int c   = blockIdx.x;             // 0..7
    const int a   = blockIdx.y;
    const int j   = c * 128 + tid;

    const float mem = mem_g[a];
    const float nid = -L2E / diff[j];

    for (int i = tid; i < LXN; i += 128) { csh[i] = g_coef[a * LXN + i]; lxsh[i] = lx[i]; }
    if (tid < 4) lxsh[LXN + tid] = 0;
    out[((size_t)a * NTASKS + j) * TSTEPS] = 0.0f;     // t=0 slice
    __syncthreads();

    float result = 0.0f;
    float r0 = tm[(size_t)lxsh[0] * NTASKS + j];
    float r1 = tm[(size_t)lxsh[1] * NTASKS + j];
    float r2 = tm[(size_t)lxsh[2] * NTASKS + j];
    float r3 = tm[(size_t)lxsh[3] * NTASKS + j];

    const int w    = tid >> 5;
    const int lane = tid & 31;

    for (int t0 = 0; t0 < LXN; t0 += P2_TW) {
        #pragma unroll
        for (int k = 0; k < P2_TW; ++k) {
            const int t = t0 + k;
            float cur;
            if      ((k & 3) == 0) cur = r0;
            else if ((k & 3) == 1) cur = r1;
            else if ((k & 3) == 2) cur = r2;
            else                   cur = r3;
            const float rn = tm[(size_t)lxsh[t + 4] * NTASKS + j];
            if      ((k & 3) == 0) r0 = rn;
            else if ((k & 3) == 1) r1 = rn;
            else if ((k & 3) == 2) r2 = rn;
            else                   r3 = rn;

            result = fmaf(result, mem, cur * csh[t]);
            float e;  asm("ex2.approx.f32 %0, %1;" : "=f"(e)  : "f"(result * nid));
            float rc; asm("rcp.approx.f32 %0, %1;" : "=f"(rc) : "f"(e + 1.0f));
            tile[k][tid] = fmaf(2.0f, rc, -1.0f);
        }
        __syncthreads();
        // warp w flushes CTA-local rows [32w, 32w+32): 128B contiguous per STG
        #pragma unroll 4
        for (int i = 0; i < 32; ++i) {
            const int row = (w << 5) + i;
            out[((size_t)a * NTASKS + c * 128 + row) * TSTEPS + 1 + t0 + lane]
                = tile[lane][row];
        }
        __syncthreads();
    }
}

extern "C" void kernel_launch(void* const* d_in, const int* in_sizes, int n_in,
                              void* d_out, int out_size)
{
    const int*   lx    = (const int*)  d_in[0];
    const float* tm    = (const float*)d_in[1];
    const float* diff  = (const float*)d_in[2];
    const float* eff   = (const float*)d_in[3];
    const float* mem   = (const float*)d_in[4];
    const float* boost = (const float*)d_in[5];
    float*       out   = (float*)d_out;

    dummy_kernel<<<1, 32>>>();
    prep_kernel<<<LXN, LXN>>>(lx, tm, diff);
    phase1_kernel<<<NALGOS, P1_THREADS>>>(eff, mem, boost);
    dim3 g2(8, NALGOS);
    phase2_kernel<<<g2, 128>>>(lx, tm, diff, mem, out);
}

// round 8
// speedup vs baseline: 3.4644x; 1.1045x over previous
#include <cuda_runtime.h>
#include <cstddef>

#define NALGOS 64
#define NTASKS 1024
#define LXN    512
#define TSTEPS 513
#define L2E    1.44269504088896f

__device__ float g_GT[LXN * LXN];          // GT[s][t] = tm[lx[t]][lx[s]] (phase 1)
__device__ float g_dvec[LXN];              // -log2e / diff[lx[s]]
__device__ float g_coef[NALGOS * LXN];     // phase-1 output
__device__ float g_Gq[130 * 4096];         // Gq[tq][j][k] = tm[lx[4tq+k]][j], +2 pad rows

// Shifts the ncu -s 5 capture slot onto a real kernel.
__global__ void dummy_kernel() {}

// ---------------------------------------------------------------------------
// prep: build GT (slot-major, coalesced writes) + dvec.   (phase-1 input)
// ---------------------------------------------------------------------------
__global__ void prep_kernel(const int*   __restrict__ lx,
                            const float* __restrict__ tm,
                            const float* __restrict__ diff)
{
    const int s  = blockIdx.x;
    const int t  = threadIdx.x;
    const int ls = lx[s];
    const int lt = lx[t];
    g_GT[s * LXN + t] = tm[(size_t)lt * NTASKS + ls];
    if (s == 0) g_dvec[t] = -L2E / diff[lt];
}

// ---------------------------------------------------------------------------
// prep2: step-major gather for phase 2. Thread (tq, j) packs steps
// 4tq..4tq+3 of column j into one float4 -> phase 2 reads 1 LDG.128 / 4 steps.
// ---------------------------------------------------------------------------
__global__ void prep2_kernel(const int* __restrict__ lx,
                             const float* __restrict__ tm)
{
    const int tq = blockIdx.x;      // 0..127
    const int j  = threadIdx.x;     // 0..1023
    const int t  = tq * 4;
    float4 v;
    v.x = tm[(size_t)lx[t + 0] * NTASKS + j];
    v.y = tm[(size_t)lx[t + 1] * NTASKS + j];
    v.z = tm[(size_t)lx[t + 2] * NTASKS + j];
    v.w = tm[(size_t)lx[t + 3] * NTASKS + j];
    ((float4*)g_Gq)[tq * 1024 + j] = v;
}

// ---------------------------------------------------------------------------
// phase 1: one CTA per algo, 544 threads. Leader warp runs the serial chain
// (affine-in-rcp trick: x_{k+1} = A + B*r_k, chain = fma->ex2->add->rcp).
// Followers batch-apply finished 32-coef blocks to future slots.
// ---------------------------------------------------------------------------
#define P1_THREADS 544

__global__ void __launch_bounds__(P1_THREADS, 1)
phase1_kernel(const float* __restrict__ eff_g,
              const float* __restrict__ mem_g,
              const float* __restrict__ boost_g)
{
    __shared__ float Gd_sh[32][33];
    __shared__ float coef_sh[LXN];
    __shared__ float dvec_sh[LXN];
    __shared__ float handoff[32];
    __shared__ float mp_sh[32];
    __shared__ float mem32_sh;

    const int tid  = threadIdx.x;
    const int w    = tid >> 5;
    const int lane = tid & 31;
    const int a    = blockIdx.x;

    const float eff   = eff_g[a];
    const float mem   = mem_g[a];
    const float boost = boost_g[a];
    const float c0    = eff - boost;
    const float c1    = 2.0f * boost;

    if (tid < LXN) dvec_sh[tid] = g_dvec[tid];
    if (tid == 0) {
        float p = 1.0f;
        for (int i = 31; i >= 0; --i) { mp_sh[i] = p; p *= mem; }
        mem32_sh = p;
    }
    for (int i = tid; i < 1024; i += P1_THREADS) {
        const int r_ = i >> 5, k_ = i & 31;
        Gd_sh[r_][k_] = g_GT[r_ * LXN + k_] * g_dvec[r_];
    }

    const int fb   = w - 1;
    const int slot = fb * 32 + lane;
    float res = 0.0f;

    float4 gt[8];
    if (w >= 1) {
        const float4* p = (const float4*)(g_GT + (size_t)slot * LXN);
        #pragma unroll
        for (int q = 0; q < 8; ++q) gt[q] = p[q];
    }
    __syncthreads();

    float tile_reg[2];

    for (int m = 0; m < 16; ++m) {
        if (m > 0) {
            {
                int q = 0;
                for (int i = tid - 32; i >= 0 && i < 1024; i += 512, ++q)
                    Gd_sh[i >> 5][i & 31] = tile_reg[q];
            }
            if (w >= 1 && fb >= m) {
                const float* cf = coef_sh + (m - 1) * 32;
                float a0 = 0.f, a1 = 0.f, a2 = 0.f, a3 = 0.f;
                const float* gf = (const float*)gt;
                #pragma unroll
                for (int i = 0; i < 32; i += 4) {
                    a0 = fmaf(gf[i + 0], cf[i + 0] * mp_sh[i + 0], a0);
                    a1 = fmaf(gf[i + 1], cf[i + 1] * mp_sh[i + 1], a1);
                    a2 = fmaf(gf[i + 2], cf[i + 2] * mp_sh[i + 2], a2);
                    a3 = fmaf(gf[i + 3], cf[i + 3] * mp_sh[i + 3], a3);
                }
                res = fmaf(res, mem32_sh, (a0 + a1) + (a2 + a3));
            }
            if (w >= 1 && fb == m) handoff[lane] = res * dvec_sh[slot];
        } else {
            if (w == 1) handoff[lane] = 0.0f;
        }
        __syncthreads();

        if (w == 0) {
            float bd[32];
            #pragma unroll
            for (int i = 0; i < 32; ++i) bd[i] = handoff[i];
            const int tb = m * 32;

            float e, r, coef;
            float x = bd[0];
            asm("ex2.approx.f32 %0, %1;" : "=f"(e) : "f"(x));
            asm("rcp.approx.f32 %0, %1;" : "=f"(r) : "f"(e + 1.0f));
            coef = fmaf(c1, r, c0);
            if (lane == 0) coef_sh[tb] = coef;
            #pragma unroll
            for (int i = 2; i < 32; ++i)
                bd[i] = fmaf(bd[i], mem, Gd_sh[i][0] * coef);

            #pragma unroll
            for (int k = 1; k < 32; ++k) {
                const float g = Gd_sh[k][k - 1];
                const float A = fmaf(bd[k], mem, g * c0);
                const float B = g * c1;
                x = fmaf(B, r, A);
                asm("ex2.approx.f32 %0, %1;" : "=f"(e) : "f"(x));
                asm("rcp.approx.f32 %0, %1;" : "=f"(r) : "f"(e + 1.0f));
                coef = fmaf(c1, r, c0);
                if (lane == 0) coef_sh[tb + k] = coef;
                #pragma unroll
                for (int i = k + 2; i < 32; ++i)
                    bd[i] = fmaf(bd[i], mem, Gd_sh[i][k] * coef);
            }
        } else {
            if (fb > m) {
                const float4* p = (const float4*)(g_GT + (size_t)slot * LXN + m * 32);
                #pragma unroll
                for (int q = 0; q < 8; ++q) gt[q] = p[q];
            }
            if (m < 15) {
                const int base = 32 * (m + 1);
                int q = 0;
                for (int i = tid - 32; i >= 0 && i < 1024; i += 512, ++q) {
                    const int s_ = base + (i >> 5);
                    tile_reg[q] = g_GT[(size_t)s_ * LXN + base + (i & 31)] * dvec_sh[s_];
                }
            }
        }
        __syncthreads();
    }

    if (tid < LXN) g_coef[a * LXN + tid] = coef_sh[tid];
}

// ---------------------------------------------------------------------------
// phase 2: independent scans. grid (8, 64) x 128 threads, occ 4.
// Per 4 steps: 1 LDG.128 (Gq stream, distance-8 via 2 buffers) + 1 LDS.128
// (coef) + 4 x {mul, fma, mul, tanh, STS}. Sigmoid is output-only here, so
// tanh.approx is safe (no feedback). Proven transposed-tile coalesced flush.
// ---------------------------------------------------------------------------
#define P2_TW 32

__global__ void __launch_bounds__(128, 4)
phase2_kernel(const float* __restrict__ diffp,
              const float* __restrict__ mem_g,
              float*       __restrict__ out)
{
    __shared__ float tile[P2_TW][129];
    __shared__ __align__(16) float csh[LXN];

    const int tid = threadIdx.x;
    const int c   = blockIdx.x;             // 0..7
    const int a   = blockIdx.y;
    const int j   = c * 128 + tid;

    const float mem = mem_g[a];
    const float hid = 0.5f / diffp[j];      // 2*sigmoid(x/d)-1 = tanh(x/(2d))

    for (int i = tid; i < LXN; i += 128) csh[i] = g_coef[a * LXN + i];
    out[((size_t)a * NTASKS + j) * TSTEPS] = 0.0f;     // t=0 slice
    __syncthreads();

    const float4* __restrict__ Gq = (const float4*)g_Gq;   // [tq][1024]
    float4 b0 = Gq[0 * 1024 + j];
    float4 b1 = Gq[1 * 1024 + j];

    float result = 0.0f;
    const int w    = tid >> 5;
    const int lane = tid & 31;

    for (int t0 = 0; t0 < LXN; t0 += P2_TW) {
        #pragma unroll
        for (int q = 0; q < 8; ++q) {
            const int tq = (t0 >> 2) + q;
            const float4 cur = (q & 1) ? b1 : b0;
            const float4 nb  = Gq[(tq + 2) * 1024 + j];    // distance-8 prefetch
            if (q & 1) b1 = nb; else b0 = nb;
            const float4 cf  = *(const float4*)&csh[tq << 2];

            float s;
            result = fmaf(result, mem, cur.x * cf.x);
            asm("tanh.approx.f32 %0, %1;" : "=f"(s) : "f"(result * hid));
            tile[q * 4 + 0][tid] = s;
            result = fmaf(result, mem, cur.y * cf.y);
            asm("tanh.approx.f32 %0, %1;" : "=f"(s) : "f"(result * hid));
            tile[q * 4 + 1][tid] = s;
            result = fmaf(result, mem, cur.z * cf.z);
            asm("tanh.approx.f32 %0, %1;" : "=f"(s) : "f"(result * hid));
            tile[q * 4 + 2][tid] = s;
            result = fmaf(result, mem, cur.w * cf.w);
            asm("tanh.approx.f32 %0, %1;" : "=f"(s) : "f"(result * hid));
            tile[q * 4 + 3][tid] = s;
        }
        __syncthreads();
        // warp w flushes CTA-local rows [32w, 32w+32): 128B contiguous per STG
        #pragma unroll 4
        for (int i = 0; i < 32; ++i) {
            const int row = (w << 5) + i;
            out[((size_t)a * NTASKS + c * 128 + row) * TSTEPS + 1 + t0 + lane]
                = tile[lane][row];
        }
        __syncthreads();
    }
}

extern "C" void kernel_launch(void* const* d_in, const int* in_sizes, int n_in,
                              void* d_out, int out_size)
{
    const int*   lx    = (const int*)  d_in[0];
    const float* tm    = (const float*)d_in[1];
    const float* diff  = (const float*)d_in[2];
    const float* eff   = (const float*)d_in[3];
    const float* mem   = (const float*)d_in[4];
    const float* boost = (const float*)d_in[5];
    float*       out   = (float*)d_out;

    dummy_kernel<<<1, 32>>>();
    prep_kernel<<<LXN, LXN>>>(lx, tm, diff);
    prep2_kernel<<<128, 1024>>>(lx, tm);
    phase1_kernel<<<NALGOS, P1_THREADS>>>(eff, mem, boost);
    dim3 g2(8, NALGOS);
    phase2_kernel<<<g2, 128>>>(diff, mem, out);
}

// round 9
// speedup vs baseline: 3.7684x; 1.0878x over previous
#include <cuda_runtime.h>
#include <cstddef>

#define NALGOS 64
#define NTASKS 1024
#define LXN    512
#define TSTEPS 513
#define L2E    1.44269504088896f

__device__ float g_GT[LXN * LXN];          // GT[s][t] = tm[lx[t]][lx[s]] (phase 1)
__device__ float g_dvec[LXN];              // -log2e / diff[lx[s]]
__device__ float g_coef[NALGOS * LXN];     // phase-1 output
__device__ float g_Gq[132 * 4096];         // Gq[tq][j][k] = tm[lx[4tq+k]][j] (+4 pad rows)

// ---------------------------------------------------------------------------
// prep: build GT (slot-major, coalesced writes) + dvec.   (phase-1 input)
// ---------------------------------------------------------------------------
__global__ void prep_kernel(const int*   __restrict__ lx,
                            const float* __restrict__ tm,
                            const float* __restrict__ diff)
{
    const int s  = blockIdx.x;
    const int t  = threadIdx.x;
    const int ls = lx[s];
    const int lt = lx[t];
    g_GT[s * LXN + t] = tm[(size_t)lt * NTASKS + ls];
    if (s == 0) g_dvec[t] = -L2E / diff[lt];
}

// ---------------------------------------------------------------------------
// prep2: step-major gather for phase 2 (1 LDG.128 per 4 steps downstream).
// ---------------------------------------------------------------------------
__global__ void prep2_kernel(const int* __restrict__ lx,
                             const float* __restrict__ tm)
{
    const int tq = blockIdx.x;      // 0..127
    const int j  = threadIdx.x;     // 0..1023
    const int t  = tq * 4;
    float4 v;
    v.x = tm[(size_t)lx[t + 0] * NTASKS + j];
    v.y = tm[(size_t)lx[t + 1] * NTASKS + j];
    v.z = tm[(size_t)lx[t + 2] * NTASKS + j];
    v.w = tm[(size_t)lx[t + 3] * NTASKS + j];
    ((float4*)g_Gq)[tq * 1024 + j] = v;
}

// ---------------------------------------------------------------------------
// phase 1: one CTA per algo, 544 threads.
// Leader warp: lane i owns in-block slot state bd[i] (ONE register). Per step:
// all lanes run the affine-rcp chain (fma->ex2->add->rcp, 40 cyc) redundantly;
// slot update is one predicated FMA per lane; bd[k+1] (pre-update) is shfl'd
// one step ahead, hidden under the MUFU chain. Followers batch-apply finished
// 32-coef blocks to their future slots (unchanged).
// ---------------------------------------------------------------------------
#define P1_THREADS 544

__global__ void __launch_bounds__(P1_THREADS, 1)
phase1_kernel(const float* __restrict__ eff_g,
              const float* __restrict__ mem_g,
              const float* __restrict__ boost_g)
{
    __shared__ float Gd_sh[32][33];   // dvec-scaled diagonal tile of current block
    __shared__ float coef_sh[LXN];
    __shared__ float dvec_sh[LXN];
    __shared__ float handoff[32];
    __shared__ float mp_sh[32];       // mem^(31-i)
    __shared__ float mem32_sh;

    const int tid  = threadIdx.x;
    const int w    = tid >> 5;
    const int lane = tid & 31;
    const int a    = blockIdx.x;

    const float eff   = eff_g[a];
    const float mem   = mem_g[a];
    const float boost = boost_g[a];
    const float c0    = eff - boost;     // coef = c0 + c1 * rcp(1+2^bd)
    const float c1    = 2.0f * boost;

    if (tid < LXN) dvec_sh[tid] = g_dvec[tid];
    if (tid == 0) {
        float p = 1.0f;
        for (int i = 31; i >= 0; --i) { mp_sh[i] = p; p *= mem; }
        mem32_sh = p;
    }
    for (int i = tid; i < 1024; i += P1_THREADS) {
        const int r_ = i >> 5, k_ = i & 31;
        Gd_sh[r_][k_] = g_GT[r_ * LXN + k_] * g_dvec[r_];
    }

    const int fb   = w - 1;           // follower's slot block (w>=1)
    const int slot = fb * 32 + lane;
    float res = 0.0f;

    float4 gt[8];                     // raw G row chunk for batch updates
    if (w >= 1) {
        const float4* p = (const float4*)(g_GT + (size_t)slot * LXN);
        #pragma unroll
        for (int q = 0; q < 8; ++q) gt[q] = p[q];
    }
    __syncthreads();

    float tile_reg[2];

    for (int m = 0; m < 16; ++m) {
        if (m > 0) {
            {   // stage tile m from prefetched regs
                int q = 0;
                for (int i = tid - 32; i >= 0 && i < 1024; i += 512, ++q)
                    Gd_sh[i >> 5][i & 31] = tile_reg[q];
            }
            if (w >= 1 && fb >= m) {
                const float* cf = coef_sh + (m - 1) * 32;
                float a0 = 0.f, a1 = 0.f, a2 = 0.f, a3 = 0.f;
                const float* gf = (const float*)gt;
                #pragma unroll
                for (int i = 0; i < 32; i += 4) {
                    a0 = fmaf(gf[i + 0], cf[i + 0] * mp_sh[i + 0], a0);
                    a1 = fmaf(gf[i + 1], cf[i + 1] * mp_sh[i + 1], a1);
                    a2 = fmaf(gf[i + 2], cf[i + 2] * mp_sh[i + 2], a2);
                    a3 = fmaf(gf[i + 3], cf[i + 3] * mp_sh[i + 3], a3);
                }
                res = fmaf(res, mem32_sh, (a0 + a1) + (a2 + a3));
            }
            if (w >= 1 && fb == m) handoff[lane] = res * dvec_sh[slot];
        } else {
            if (w == 1) handoff[lane] = 0.0f;
        }
        __syncthreads();

        if (w == 0) {
            float bd = handoff[lane];          // lane's slot state (dvec-scaled)
            const int tb = m * 32;

            // step 0
            float e, r;
            float x = __shfl_sync(0xffffffffu, bd, 0);
            asm("ex2.approx.f32 %0, %1;" : "=f"(e) : "f"(x));
            asm("rcp.approx.f32 %0, %1;" : "=f"(r) : "f"(e + 1.0f));
            float coef = fmaf(c1, r, c0);
            if (lane == 0) coef_sh[tb] = coef;
            float bcast = __shfl_sync(0xffffffffu, bd, 1);   // bd[1] pre-update
            if (lane > 0) bd = fmaf(bd, mem, Gd_sh[lane][0] * coef);

            // steps 1..31: x_k = A + B*r_{k-1}; A,B off the critical path
            #pragma unroll
            for (int k = 1; k < 32; ++k) {
                const float g = Gd_sh[k][k - 1];             // uniform -> broadcast
                const float A = fmaf(bcast, mem, g * c0);
                const float B = g * c1;
                x = fmaf(B, r, A);
                bcast = __shfl_sync(0xffffffffu, bd, k + 1); // bd[k+1]^{(k-1)}, pre-update
                asm("ex2.approx.f32 %0, %1;" : "=f"(e) : "f"(x));
                asm("rcp.approx.f32 %0, %1;" : "=f"(r) : "f"(e + 1.0f));
                coef = fmaf(c1, r, c0);
                if (lane == 0) coef_sh[tb + k] = coef;
                if (lane > k) bd = fmaf(bd, mem, Gd_sh[lane][k] * coef);
            }
        } else {
            if (fb > m) {   // prefetch raw-G chunk for block-m coefs
                const float4* p = (const float4*)(g_GT + (size_t)slot * LXN + m * 32);
                #pragma unroll
                for (int q = 0; q < 8; ++q) gt[q] = p[q];
            }
            if (m < 15) {   // prefetch next diagonal tile, dvec-scaled
                const int base = 32 * (m + 1);
                int q = 0;
                for (int i = tid - 32; i >= 0 && i < 1024; i += 512, ++q) {
                    const int s_ = base + (i >> 5);
                    tile_reg[q] = g_GT[(size_t)s_ * LXN + base + (i & 31)] * dvec_sh[s_];
                }
            }
        }
        __syncthreads();
    }

    if (tid < LXN) g_coef[a * LXN + tid] = coef_sh[tid];
}

// ---------------------------------------------------------------------------
// phase 2: independent scans, TWO algos per CTA (Gq stream shared -> L2 reads
// halved; two independent chains double ILP). grid (8 chunks, 32 pairs) x 128.
// 4-deep float4 prefetch ring (16-step distance) fully covers L2 latency.
// tanh.approx is output-only here (coef from phase 1, no feedback) -> safe.
// ---------------------------------------------------------------------------
#define P2_TW 32

__global__ void __launch_bounds__(128, 2)
phase2_kernel(const float* __restrict__ diffp,
              const float* __restrict__ mem_g,
              float*       __restrict__ out)
{
    __shared__ float tileA[P2_TW][129];
    __shared__ float tileB[P2_TW][129];
    __shared__ __align__(16) float csh[2][LXN];

    const int tid = threadIdx.x;
    const int c   = blockIdx.x;             // 0..7
    const int p   = blockIdx.y;             // 0..31
    const int a0  = 2 * p, a1 = 2 * p + 1;
    const int j   = c * 128 + tid;

    const float mem0 = mem_g[a0];
    const float mem1 = mem_g[a1];
    const float hid  = 0.5f / diffp[j];     // 2*sigmoid(x/d)-1 = tanh(x/(2d))

    for (int i = tid; i < LXN; i += 128) {
        csh[0][i] = g_coef[a0 * LXN + i];
        csh[1][i] = g_coef[a1 * LXN + i];
    }
    out[((size_t)a0 * NTASKS + j) * TSTEPS] = 0.0f;    // t=0 slices
    out[((size_t)a1 * NTASKS + j) * TSTEPS] = 0.0f;
    __syncthreads();

    const float4* __restrict__ Gq = (const float4*)g_Gq;   // [tq][1024]
    float4 b[4];
    #pragma unroll
    for (int q = 0; q < 4; ++q) b[q] = Gq[q * 1024 + j];

    float res0 = 0.0f, res1 = 0.0f;
    const int w    = tid >> 5;
    const int lane = tid & 31;

    for (int t0 = 0; t0 < LXN; t0 += P2_TW) {
        #pragma unroll
        for (int q = 0; q < 8; ++q) {
            const int tq = (t0 >> 2) + q;
            const float4 cur = b[q & 3];
            b[q & 3] = Gq[(tq + 4) * 1024 + j];        // distance-16 prefetch
            const float4 cf0 = *(const float4*)&csh[0][tq << 2];
            const float4 cf1 = *(const float4*)&csh[1][tq << 2];
            float s;
            res0 = fmaf(res0, mem0, cur.x * cf0.x);
            asm("tanh.approx.f32 %0, %1;" : "=f"(s) : "f"(res0 * hid));
            tileA[q * 4 + 0][tid] = s;
            res1 = fmaf(res1, mem1, cur.x * cf1.x);
            asm("tanh.approx.f32 %0, %1;" : "=f"(s) : "f"(res1 * hid));
            tileB[q * 4 + 0][tid] = s;

            res0 = fmaf(res0, mem0, cur.y * cf0.y);
            asm("tanh.approx.f32 %0, %1;" : "=f"(s) : "f"(res0 * hid));
            tileA[q * 4 + 1][tid] = s;
            res1 = fmaf(res1, mem1, cur.y * cf1.y);
            asm("tanh.approx.f32 %0, %1;" : "=f"(s) : "f"(res1 * hid));
            tileB[q * 4 + 1][tid] = s;

            res0 = fmaf(res0, mem0, cur.z * cf0.z);
            asm("tanh.approx.f32 %0, %1;" : "=f"(s) : "f"(res0 * hid));
            tileA[q * 4 + 2][tid] = s;
            res1 = fmaf(res1, mem1, cur.z * cf1.z);
            asm("tanh.approx.f32 %0, %1;" : "=f"(s) : "f"(res1 * hid));
            tileB[q * 4 + 2][tid] = s;

            res0 = fmaf(res0, mem0, cur.w * cf0.w);
            asm("tanh.approx.f32 %0, %1;" : "=f"(s) : "f"(res0 * hid));
            tileA[q * 4 + 3][tid] = s;
            res1 = fmaf(res1, mem1, cur.w * cf1.w);
            asm("tanh.approx.f32 %0, %1;" : "=f"(s) : "f"(res1 * hid));
            tileB[q * 4 + 3][tid] = s;
        }
        __syncthreads();
        // warp w flushes CTA-local rows [32w, 32w+32) for both algos:
        // 128B contiguous per STG.
        #pragma unroll 2
        for (int i = 0; i < 32; ++i) {
            const int row = (w << 5) + i;
            const size_t tcol = (size_t)(1 + t0 + lane);
            out[((size_t)a0 * NTASKS + c * 128 + row) * TSTEPS + tcol]
                = tileA[lane][row];
            out[((size_t)a1 * NTASKS + c * 128 + row) * TSTEPS + tcol]
                = tileB[lane][row];
        }
        __syncthreads();
    }
}

extern "C" void kernel_launch(void* const* d_in, const int* in_sizes, int n_in,
                              void* d_out, int out_size)
{
    const int*   lx    = (const int*)  d_in[0];
    const float* tm    = (const float*)d_in[1];
    const float* diff  = (const float*)d_in[2];
    const float* eff   = (const float*)d_in[3];
    const float* mem   = (const float*)d_in[4];
    const float* boost = (const float*)d_in[5];
    float*       out   = (float*)d_out;

    prep_kernel<<<LXN, LXN>>>(lx, tm, diff);
    prep2_kernel<<<128, 1024>>>(lx, tm);
    phase1_kernel<<<NALGOS, P1_THREADS>>>(eff, mem, boost);
    dim3 g2(8, 32);
    phase2_kernel<<<g2, 128>>>(diff, mem, out);   // launch #4 -> ncu capture slot
}

// round 12
// speedup vs baseline: 3.9645x; 1.0520x over previous
#include <cuda_runtime.h>
#include <cstddef>

#define NALGOS 64
#define NTASKS 1024
#define LXN    512
#define TSTEPS 513
#define L2E    1.44269504088896f

__device__ float g_GT[LXN * LXN];          // GT[s][t] = tm[lx[t]][lx[s]] (phase 1)
__device__ float g_dvec[LXN];              // -log2e / diff[lx[s]]
__device__ float g_coef[NALGOS * LXN];     // phase-1 output
__device__ float g_Gq[132 * 4096];         // Gq[tq][j][k] = tm[lx[4tq+k]][j] (+4 pad rows)

__global__ void dummy_kernel() {}          // shifts ncu capture slot -> phase1

// ---------------------------------------------------------------------------
// prep: build GT (slot-major, coalesced writes) + dvec.
// ---------------------------------------------------------------------------
__global__ void prep_kernel(const int*   __restrict__ lx,
                            const float* __restrict__ tm,
                            const float* __restrict__ diff)
{
    const int s  = blockIdx.x;
    const int t  = threadIdx.x;
    const int ls = lx[s];
    const int lt = lx[t];
    g_GT[s * LXN + t] = tm[(size_t)lt * NTASKS + ls];
    if (s == 0) g_dvec[t] = -L2E / diff[lt];
}

// ---------------------------------------------------------------------------
// prep2: step-major gather for phase 2 (1 LDG.128 per 4 steps downstream).
// ---------------------------------------------------------------------------
__global__ void prep2_kernel(const int* __restrict__ lx,
                             const float* __restrict__ tm)
{
    const int tq = blockIdx.x;      // 0..127
    const int j  = threadIdx.x;     // 0..1023
    const int t  = tq * 4;
    float4 v;
    v.x = tm[(size_t)lx[t + 0] * NTASKS + j];
    v.y = tm[(size_t)lx[t + 1] * NTASKS + j];
    v.z = tm[(size_t)lx[t + 2] * NTASKS + j];
    v.w = tm[(size_t)lx[t + 3] * NTASKS + j];
    ((float4*)g_Gq)[tq * 1024 + j] = v;
}

// ---------------------------------------------------------------------------
// phase 1: one CTA per algo, 544 threads. Leader warp: lane i owns slot i of
// the current 32-step block. Serial chain uses a TWO-step-lookahead shfl:
// S = bd[k+2] (coefs through k-1 only), then
//   x_{k+2} = S*mem^2 + g1*mem*coef_k + g2*coef_{k+1} = A + B1*r_k + B2*r_{k+1}
// so the shfl has >= 40 cyc slack and the serial path is fma->ex2->add->rcp.
// ---------------------------------------------------------------------------
#define P1_THREADS 544

__global__ void __launch_bounds__(P1_THREADS, 1)
phase1_kernel(const float* __restrict__ eff_g,
              const float* __restrict__ mem_g,
              const float* __restrict__ boost_g)
{
    __shared__ float Gd_sh[32][33];   // dvec-scaled diagonal tile of current block
    __shared__ float coef_sh[LXN];
    __shared__ float dvec_sh[LXN];
    __shared__ float handoff[32];
    __shared__ float mp_sh[32];       // mem^(31-i)
    __shared__ float mem32_sh;

    const int tid  = threadIdx.x;
    const int w    = tid >> 5;
    const int lane = tid & 31;
    const int a    = blockIdx.x;

    const float eff   = eff_g[a];
    const float mem   = mem_g[a];
    const float boost = boost_g[a];
    const float c0    = eff - boost;     // coef = c0 + c1 * rcp(1+2^bd)
    const float c1    = 2.0f * boost;

    if (tid < LXN) dvec_sh[tid] = g_dvec[tid];
    if (tid == 0) {
        float p = 1.0f;
        for (int i = 31; i >= 0; --i) { mp_sh[i] = p; p *= mem; }
        mem32_sh = p;
    }
    for (int i = tid; i < 1024; i += P1_THREADS) {
        const int r_ = i >> 5, k_ = i & 31;
        Gd_sh[r_][k_] = g_GT[r_ * LXN + k_] * g_dvec[r_];
    }

    const int fb   = w - 1;           // follower's slot block (w>=1)
    const int slot = fb * 32 + lane;
    float res = 0.0f;

    float4 gt[8];                     // raw G row chunk for batch updates
    if (w >= 1) {
        const float4* p = (const float4*)(g_GT + (size_t)slot * LXN);
        #pragma unroll
        for (int q = 0; q < 8; ++q) gt[q] = p[q];
    }
    __syncthreads();

    float tile_reg[2];

    for (int m = 0; m < 16; ++m) {
        if (m > 0) {
            {   // stage tile m from prefetched regs
                int q = 0;
                for (int i = tid - 32; i >= 0 && i < 1024; i += 512, ++q)
                    Gd_sh[i >> 5][i & 31] = tile_reg[q];
            }
            if (w >= 1 && fb >= m) {
                const float* cf = coef_sh + (m - 1) * 32;
                float a0 = 0.f, a1 = 0.f, a2 = 0.f, a3 = 0.f;
                const float* gf = (const float*)gt;
                #pragma unroll
                for (int i = 0; i < 32; i += 4) {
                    a0 = fmaf(gf[i + 0], cf[i + 0] * mp_sh[i + 0], a0);
                    a1 = fmaf(gf[i + 1], cf[i + 1] * mp_sh[i + 1], a1);
                    a2 = fmaf(gf[i + 2], cf[i + 2] * mp_sh[i + 2], a2);
                    a3 = fmaf(gf[i + 3], cf[i + 3] * mp_sh[i + 3], a3);
                }
                res = fmaf(res, mem32_sh, (a0 + a1) + (a2 + a3));
            }
            if (w >= 1 && fb == m) handoff[lane] = res * dvec_sh[slot];
        } else {
            if (w == 1) handoff[lane] = 0.0f;
        }
        __syncthreads();

        if (w == 0) {
            float bd = handoff[lane];
            const int tb   = m * 32;
            const float mem2 = mem * mem;

            float x  = __shfl_sync(0xffffffffu, bd, 0);           // x_0
            float b1 = __shfl_sync(0xffffffffu, bd, 1);
            const float g10 = Gd_sh[1][0];
            float Pn  = fmaf(b1, mem, g10 * c0);                  // A_1 (no r_{-1} term)
            float B2n = g10 * c1;

            float e, r;
            #pragma unroll
            for (int k = 0; k < 32; ++k) {
                float S = 0.0f;
                if (k < 30) S = __shfl_sync(0xffffffffu, bd, k + 2); // coefs thru k-1
                asm("ex2.approx.f32 %0, %1;" : "=f"(e) : "f"(x));
                asm("rcp.approx.f32 %0, %1;" : "=f"(r) : "f"(e + 1.0f));
                const float coef = fmaf(c1, r, c0);
                if (lane == 0) coef_sh[tb + k] = coef;

                if (k < 31) x = fmaf(B2n, r, Pn);                 // x_{k+1}

                if (k < 30) {                                     // prep x_{k+2}
                    const float g1 = Gd_sh[k + 2][k];
                    const float g2 = Gd_sh[k + 2][k + 1];
                    const float A  = fmaf(S, mem2, fmaf(g1, mem, g2) * c0);
                    Pn  = fmaf(g1 * mem * c1, r, A);
                    B2n = g2 * c1;
                }
                if (lane > k) bd = fmaf(bd, mem, Gd_sh[lane][k] * coef);
            }
        } else {
            if (fb > m) {   // prefetch raw-G chunk for block-m coefs
                const float4* p = (const float4*)(g_GT + (size_t)slot * LXN + m * 32);
                #pragma unroll
                for (int q = 0; q < 8; ++q) gt[q] = p[q];
            }
            if (m < 15) {   // prefetch next diagonal tile, dvec-scaled
                const int base = 32 * (m + 1);
                int q = 0;
                for (int i = tid - 32; i >= 0 && i < 1024; i += 512, ++q) {
                    const int s_ = base + (i >> 5);
                    tile_reg[q] = g_GT[(size_t)s_ * LXN + base + (i & 31)] * dvec_sh[s_];
                }
            }
        }
        __syncthreads();
    }

    if (tid < LXN) g_coef[a * LXN + tid] = coef_sh[tid];
}

// ---------------------------------------------------------------------------
// phase 2: independent scans, two algos per CTA. The 32x32 output transpose
// is WARP-PRIVATE (warp w writes tile columns [32w,32w+32) and flushes those
// same columns) -> __syncwarp() instead of __syncthreads(): no CTA convoy.
// ---------------------------------------------------------------------------
#define P2_TW 32

__global__ void __launch_bounds__(128, 2)
phase2_kernel(const float* __restrict__ diffp,
              const float* __restrict__ mem_g,
              float*       __restrict__ out)
{
    __shared__ float tileA[P2_TW][129];
    __shared__ float tileB[P2_TW][129];
    __shared__ __align__(16) float csh[2][LXN];

    const int tid = threadIdx.x;
    const int c   = blockIdx.x;             // 0..7
    const int p   = blockIdx.y;             // 0..31
    const int a0  = 2 * p, a1 = 2 * p + 1;
    const int j   = c * 128 + tid;

    const float mem0 = mem_g[a0];
    const float mem1 = mem_g[a1];
    const float hid  = 0.5f / diffp[j];     // 2*sigmoid(x/d)-1 = tanh(x/(2d))

    for (int i = tid; i < LXN; i += 128) {
        csh[0][i] = g_coef[a0 * LXN + i];
        csh[1][i] = g_coef[a1 * LXN + i];
    }
    out[((size_t)a0 * NTASKS + j) * TSTEPS] = 0.0f;    // t=0 slices
    out[((size_t)a1 * NTASKS + j) * TSTEPS] = 0.0f;
    __syncthreads();

    const float4* __restrict__ Gq = (const float4*)g_Gq;   // [tq][1024]
    float4 b[4];
    #pragma unroll
    for (int q = 0; q < 4; ++q) b[q] = Gq[q * 1024 + j];

    float res0 = 0.0f, res1 = 0.0f;
    const int w    = tid >> 5;
    const int lane = tid & 31;

    for (int t0 = 0; t0 < LXN; t0 += P2_TW) {
        #pragma unroll
        for (int q = 0; q < 8; ++q) {
            const int tq = (t0 >> 2) + q;
            const float4 cur = b[q & 3];
            b[q & 3] = Gq[(tq + 4) * 1024 + j];        // distance-16 prefetch
            const float4 cf0 = *(const float4*)&csh[0][tq << 2];
            const float4 cf1 = *(const float4*)&csh[1][tq << 2];
            float s;
            res0 = fmaf(res0, mem0, cur.x * cf0.x);
            asm("tanh.approx.f32 %0, %1;" : "=f"(s) : "f"(res0 * hid));
            tileA[q * 4 + 0][tid] = s;
            res1 = fmaf(res1, mem1, cur.x * cf1.x);
            asm("tanh.approx.f32 %0, %1;" : "=f"(s) : "f"(res1 * hid));
            tileB[q * 4 + 0][tid] = s;

            res0 = fmaf(res0, mem0, cur.y * cf0.y);
            asm("tanh.approx.f32 %0, %1;" : "=f"(s) : "f"(res0 * hid));
            tileA[q * 4 + 1][tid] = s;
            res1 = fmaf(res1, mem1, cur.y * cf1.y);
            asm("tanh.approx.f32 %0, %1;" : "=f"(s) : "f"(res1 * hid));
            tileB[q * 4 + 1][tid] = s;

            res0 = fmaf(res0, mem0, cur.z * cf0.z);
            asm("tanh.approx.f32 %0, %1;" : "=f"(s) : "f"(res0 * hid));
            tileA[q * 4 + 2][tid] = s;
            res1 = fmaf(res1, mem1, cur.z * cf1.z);
            asm("tanh.approx.f32 %0, %1;" : "=f"(s) : "f"(res1 * hid));
            tileB[q * 4 + 2][tid] = s;

            res0 = fmaf(res0, mem0, cur.w * cf0.w);
            asm("tanh.approx.f32 %0, %1;" : "=f"(s) : "f"(res0 * hid));
            tileA[q * 4 + 3][tid] = s;
            res1 = fmaf(res1, mem1, cur.w * cf1.w);
            asm("tanh.approx.f32 %0, %1;" : "=f"(s) : "f"(res1 * hid));
            tileB[q * 4 + 3][tid] = s;
        }
        __syncwarp();   // transpose is intra-warp: no CTA barrier needed
        #pragma unroll 2
        for (int i = 0; i < 32; ++i) {
            const int row = (w << 5) + i;
            const size_t tcol = (size_t)(1 + t0 + lane);
            out[((size_t)a0 * NTASKS + c * 128 + row) * TSTEPS + tcol]
                = tileA[lane][row];
            out[((size_t)a1 * NTASKS + c * 128 + row) * TSTEPS + tcol]
                = tileB[lane][row];
        }
        __syncwarp();
    }
}

extern "C" void kernel_launch(void* const* d_in, const int* in_sizes, int n_in,
                              void* d_out, int out_size)
{
    const int*   lx    = (const int*)  d_in[0];
    const float* tm    = (const float*)d_in[1];
    const float* diff  = (const float*)d_in[2];
    const float* eff   = (const float*)d_in[3];
    const float* mem   = (const float*)d_in[4];
    const float* boost = (const float*)d_in[5];
    float*       out   = (float*)d_out;

    dummy_kernel<<<1, 32>>>();
    prep_kernel<<<LXN, LXN>>>(lx, tm, diff);
    prep2_kernel<<<128, 1024>>>(lx, tm);
    phase1_kernel<<<NALGOS, P1_THREADS>>>(eff, mem, boost);   // launch #4 -> profiled
    dim3 g2(8, 32);
    phase2_kernel<<<g2, 128>>>(diff, mem, out);
}